// round 2
// baseline (speedup 1.0000x reference)
#include <cuda_runtime.h>

// GCN_12867722019091 — 2-layer GCN, N=50000 nodes, E=800000 edges, HID=64, OUT=2.
// Key insight: NUM_FEATURES=1 makes layer-1 rank-1, and propagation is linear,
// so both conv layers reduce to scalar / float2 scatter-adds over edges.

constexpr int NN  = 50000;
constexpr int NE  = 800000;
constexpr int HID = 64;

// Scratch (static __device__ — no allocation allowed)
__device__ int    g_deg[NN];
__device__ float  g_dinv[NN];
__device__ float  g_p[NN];      // x[n] * dinv[n]
__device__ float  g_s1[NN];     // scalar scatter accumulator (layer 1)
__device__ float2 g_p2[NN];     // g[n,:] * dinv[n]
__device__ float2 g_acc[NN];    // float2 scatter accumulator (layer 2)

__global__ void k_init() {
    int i = blockIdx.x * blockDim.x + threadIdx.x;
    if (i < NN) {
        g_deg[i] = 0;
        g_s1[i]  = 0.f;
        g_acc[i] = make_float2(0.f, 0.f);
    }
}

// In-degree count (self-loop added as +1 later)
__global__ void k_count(const int* __restrict__ col) {
    int i = blockIdx.x * blockDim.x + threadIdx.x;
    int base = i * 4;
    if (base >= NE) return;
    int4 c = *reinterpret_cast<const int4*>(col + base);
    atomicAdd(&g_deg[c.x], 1);
    atomicAdd(&g_deg[c.y], 1);
    atomicAdd(&g_deg[c.z], 1);
    atomicAdd(&g_deg[c.w], 1);
}

// dinv[n] = rsqrt(deg+1);  p[n] = x[n]*dinv[n]
__global__ void k_node1(const float* __restrict__ x) {
    int i = blockIdx.x * blockDim.x + threadIdx.x;
    if (i >= NN) return;
    float dinv = rsqrtf((float)(g_deg[i] + 1));
    g_dinv[i] = dinv;
    g_p[i]    = x[i] * dinv;
}

// s1_acc[c] += p[r]  (scalar per edge)
__global__ void k_scat1(const int* __restrict__ row, const int* __restrict__ col) {
    int i = blockIdx.x * blockDim.x + threadIdx.x;
    int base = i * 4;
    if (base >= NE) return;
    int4 r = *reinterpret_cast<const int4*>(row + base);
    int4 c = *reinterpret_cast<const int4*>(col + base);
    atomicAdd(&g_s1[c.x], __ldg(&g_p[r.x]));
    atomicAdd(&g_s1[c.y], __ldg(&g_p[r.y]));
    atomicAdd(&g_s1[c.z], __ldg(&g_p[r.z]));
    atomicAdd(&g_s1[c.w], __ldg(&g_p[r.w]));
}

// s1[n] = dinv*(acc + p);  h1[j] = relu(W1[j]*s1 + b1[j]);
// g[n,k] = sum_j h1[j]*W2[j,k];  p2[n,:] = g[n,:]*dinv
__global__ void k_node2(const float* __restrict__ W1, const float* __restrict__ b1,
                        const float* __restrict__ W2) {
    __shared__ float sW1[HID], sb1[HID], sW2[HID * 2];
    int t = threadIdx.x;
    if (t < HID)     { sW1[t] = W1[t]; sb1[t] = b1[t]; }
    if (t < HID * 2) { sW2[t] = W2[t]; }
    __syncthreads();

    int i = blockIdx.x * blockDim.x + t;
    if (i >= NN) return;
    float dinv = g_dinv[i];
    float s1   = dinv * (g_s1[i] + g_p[i]);
    float a = 0.f, b = 0.f;
#pragma unroll
    for (int j = 0; j < HID; ++j) {
        float h = fmaxf(fmaf(sW1[j], s1, sb1[j]), 0.f);
        a = fmaf(h, sW2[2 * j],     a);
        b = fmaf(h, sW2[2 * j + 1], b);
    }
    g_p2[i] = make_float2(a * dinv, b * dinv);
}

// acc[c] += p2[r]  (float2 per edge; sm_90+ vector atomic)
__global__ void k_scat2(const int* __restrict__ row, const int* __restrict__ col) {
    int i = blockIdx.x * blockDim.x + threadIdx.x;
    int base = i * 4;
    if (base >= NE) return;
    int4 r = *reinterpret_cast<const int4*>(row + base);
    int4 c = *reinterpret_cast<const int4*>(col + base);
#if __CUDA_ARCH__ >= 900
    atomicAdd(&g_acc[c.x], g_p2[r.x]);
    atomicAdd(&g_acc[c.y], g_p2[r.y]);
    atomicAdd(&g_acc[c.z], g_p2[r.z]);
    atomicAdd(&g_acc[c.w], g_p2[r.w]);
#else
    float2 vx = g_p2[r.x], vy = g_p2[r.y], vz = g_p2[r.z], vw = g_p2[r.w];
    atomicAdd(&g_acc[c.x].x, vx.x); atomicAdd(&g_acc[c.x].y, vx.y);
    atomicAdd(&g_acc[c.y].x, vy.x); atomicAdd(&g_acc[c.y].y, vy.y);
    atomicAdd(&g_acc[c.z].x, vz.x); atomicAdd(&g_acc[c.z].y, vz.y);
    atomicAdd(&g_acc[c.w].x, vw.x); atomicAdd(&g_acc[c.w].y, vw.y);
#endif
}

// out[n,:] = dinv*(acc + p2) + b2
__global__ void k_final(float* __restrict__ out, const float* __restrict__ b2) {
    int i = blockIdx.x * blockDim.x + threadIdx.x;
    if (i >= NN) return;
    float dinv = g_dinv[i];
    float2 acc = g_acc[i];
    float2 p2  = g_p2[i];
    float2 o;
    o.x = fmaf(dinv, acc.x + p2.x, b2[0]);
    o.y = fmaf(dinv, acc.y + p2.y, b2[1]);
    reinterpret_cast<float2*>(out)[i] = o;
}

extern "C" void kernel_launch(void* const* d_in, const int* in_sizes, int n_in,
                              void* d_out, int out_size) {
    const float* x   = (const float*)d_in[0];
    const int*   ei  = (const int*)d_in[1];   // [2, NE]: row = ei[0:NE], col = ei[NE:2NE]
    const float* W1  = (const float*)d_in[2];
    const float* b1  = (const float*)d_in[3];
    const float* W2  = (const float*)d_in[4];
    const float* b2  = (const float*)d_in[5];
    float* out = (float*)d_out;

    const int* row = ei;
    const int* col = ei + NE;

    const int TB = 256;
    const int nodeBlocks = (NN + TB - 1) / TB;
    const int edgeBlocks = (NE / 4 + TB - 1) / TB;

    k_init <<<nodeBlocks, TB>>>();
    k_count<<<edgeBlocks, TB>>>(col);
    k_node1<<<nodeBlocks, TB>>>(x);
    k_scat1<<<edgeBlocks, TB>>>(row, col);
    k_node2<<<nodeBlocks, TB>>>(W1, b1, W2);
    k_scat2<<<edgeBlocks, TB>>>(row, col);
    k_final<<<nodeBlocks, TB>>>(out, b2);
}

// round 3
// speedup vs baseline: 1.0580x; 1.0580x over previous
#include <cuda_runtime.h>

// GCN_12867722019091 — 2-layer GCN, N=50000, E=800000, HID=64, OUT=2.
// Rank-1 layer-1 + linear propagation => per-edge work is scalar / float2
// scatter-adds. Edge passes are L1tex-wavefront latency-bound: maximize
// occupancy (1 edge/thread) to keep the wavefront queue full.

constexpr int NN  = 50000;
constexpr int NE  = 800000;
constexpr int HID = 64;

// Scratch — zero-initialized at module load; k_final re-zeroes for the next
// replay, so every kernel_launch call starts from zeros (deterministic).
__device__ int    g_deg[NN];
__device__ float  g_dinv[NN];
__device__ float  g_p[NN];      // x[n] * dinv[n]
__device__ float  g_s1[NN];     // layer-1 scalar scatter accumulator
__device__ float2 g_p2[NN];     // g[n,:] * dinv[n]
__device__ float2 g_acc[NN];    // layer-2 float2 scatter accumulator

// ---- edge passes: 1 edge/thread for max occupancy / latency hiding ----

__global__ void __launch_bounds__(256) k_count(const int* __restrict__ col) {
    int i = blockIdx.x * blockDim.x + threadIdx.x;
    if (i < NE) atomicAdd(&g_deg[col[i]], 1);
}

__global__ void __launch_bounds__(256) k_scat1(const int* __restrict__ row,
                                               const int* __restrict__ col) {
    int i = blockIdx.x * blockDim.x + threadIdx.x;
    if (i < NE) {
        int r = row[i];
        int c = col[i];
        atomicAdd(&g_s1[c], __ldg(&g_p[r]));
    }
}

__global__ void __launch_bounds__(256) k_scat2(const int* __restrict__ row,
                                               const int* __restrict__ col) {
    int i = blockIdx.x * blockDim.x + threadIdx.x;
    if (i < NE) {
        int r = row[i];
        int c = col[i];
        float2 v = *reinterpret_cast<const float2*>(&g_p2[r]);
        atomicAdd(&g_acc[c], v);
    }
}

// ---- node passes ----

// dinv = rsqrt(deg+1); p = x*dinv
__global__ void __launch_bounds__(256) k_node1(const float* __restrict__ x) {
    int i = blockIdx.x * blockDim.x + threadIdx.x;
    if (i >= NN) return;
    float dinv = rsqrtf((float)(g_deg[i] + 1));
    g_dinv[i] = dinv;
    g_p[i]    = x[i] * dinv;
}

// s1 = dinv*(acc + p);  h1 = relu(W1*s1 + b1);  p2 = (h1@W2)*dinv
__global__ void __launch_bounds__(256) k_node2(const float* __restrict__ W1,
                                               const float* __restrict__ b1,
                                               const float* __restrict__ W2) {
    __shared__ float sW1[HID], sb1[HID], sW2[HID * 2];
    int t = threadIdx.x;
    if (t < HID)     { sW1[t] = W1[t]; sb1[t] = b1[t]; }
    if (t < HID * 2) { sW2[t] = W2[t]; }
    __syncthreads();

    int i = blockIdx.x * blockDim.x + t;
    if (i >= NN) return;
    float dinv = g_dinv[i];
    float s1   = dinv * (g_s1[i] + g_p[i]);
    float a = 0.f, b = 0.f;
#pragma unroll
    for (int j = 0; j < HID; ++j) {
        float h = fmaxf(fmaf(sW1[j], s1, sb1[j]), 0.f);
        a = fmaf(h, sW2[2 * j],     a);
        b = fmaf(h, sW2[2 * j + 1], b);
    }
    g_p2[i] = make_float2(a * dinv, b * dinv);
}

// out = dinv*(acc + p2) + b2 ; then reset scratch for the next replay
__global__ void __launch_bounds__(256) k_final(float* __restrict__ out,
                                               const float* __restrict__ b2) {
    int i = blockIdx.x * blockDim.x + threadIdx.x;
    if (i >= NN) return;
    float dinv = g_dinv[i];
    float2 acc = g_acc[i];
    float2 p2  = g_p2[i];
    float2 o;
    o.x = fmaf(dinv, acc.x + p2.x, b2[0]);
    o.y = fmaf(dinv, acc.y + p2.y, b2[1]);
    reinterpret_cast<float2*>(out)[i] = o;

    // restore the all-zeros invariant for the next kernel_launch call
    g_deg[i] = 0;
    g_s1[i]  = 0.f;
    g_acc[i] = make_float2(0.f, 0.f);
}

extern "C" void kernel_launch(void* const* d_in, const int* in_sizes, int n_in,
                              void* d_out, int out_size) {
    const float* x   = (const float*)d_in[0];
    const int*   ei  = (const int*)d_in[1];   // [2, NE]: row = ei[0:NE], col = ei[NE:2NE]
    const float* W1  = (const float*)d_in[2];
    const float* b1  = (const float*)d_in[3];
    const float* W2  = (const float*)d_in[4];
    const float* b2  = (const float*)d_in[5];
    float* out = (float*)d_out;

    const int* row = ei;
    const int* col = ei + NE;

    const int TB = 256;
    const int nodeBlocks = (NN + TB - 1) / TB;
    const int edgeBlocks = (NE + TB - 1) / TB;   // 1 edge per thread

    k_count<<<edgeBlocks, TB>>>(col);
    k_node1<<<nodeBlocks, TB>>>(x);
    k_scat1<<<edgeBlocks, TB>>>(row, col);
    k_node2<<<nodeBlocks, TB>>>(W1, b1, W2);
    k_scat2<<<edgeBlocks, TB>>>(row, col);
    k_final<<<nodeBlocks, TB>>>(out, b2);
}

// round 7
// speedup vs baseline: 1.1385x; 1.0761x over previous
#include <cuda_runtime.h>

// GCN_12867722019091 — 2-layer GCN, N=50000, E=800000, HID=64, OUT=2.
// Rank-1 layer-1 + linear propagation => per-edge work is scalar / float2
// scatter-adds. Edge passes are L1tex divergent-lane bound (~14us floor);
// the rest of the 35us was serialized launch + prologue latency -> hide it
// with PDL (programmatic dependent launch): prologue before griddepcontrol.wait,
// trigger dependents immediately after.

constexpr int NN  = 50000;
constexpr int NE  = 800000;
constexpr int HID = 64;

__device__ int    g_deg[NN];
__device__ float  g_dinv[NN];
__device__ float  g_p[NN];      // x[n] * dinv[n]
__device__ float  g_s1[NN];     // layer-1 scalar scatter accumulator
__device__ float2 g_p2[NN];     // g[n,:] * dinv[n]
__device__ float2 g_acc[NN];    // layer-2 float2 scatter accumulator

__device__ __forceinline__ void pdl_wait() {
#if __CUDA_ARCH__ >= 900
    asm volatile("griddepcontrol.wait;" ::: "memory");
#endif
}
__device__ __forceinline__ void pdl_trigger() {
#if __CUDA_ARCH__ >= 900
    asm volatile("griddepcontrol.launch_dependents;" ::: "memory");
#endif
}

// ---- edge passes: 1 edge/thread ----

__global__ void __launch_bounds__(256) k_count(const int* __restrict__ col) {
    int i = blockIdx.x * blockDim.x + threadIdx.x;
    int c = (i < NE) ? col[i] : 0;              // prologue: coalesced, independent
    pdl_wait();                                  // wait for prev replay's reset
    pdl_trigger();
    if (i < NE) atomicAdd(&g_deg[c], 1);
}

__global__ void __launch_bounds__(256) k_scat1(const int* __restrict__ row,
                                               const int* __restrict__ col) {
    int i = blockIdx.x * blockDim.x + threadIdx.x;
    int r = 0, c = 0;
    if (i < NE) { r = row[i]; c = col[i]; }      // prologue
    pdl_wait();                                  // g_p ready
    pdl_trigger();
    if (i < NE) atomicAdd(&g_s1[c], __ldg(&g_p[r]));
}

__global__ void __launch_bounds__(256) k_scat2(const int* __restrict__ row,
                                               const int* __restrict__ col) {
    int i = blockIdx.x * blockDim.x + threadIdx.x;
    int r = 0, c = 0;
    if (i < NE) { r = row[i]; c = col[i]; }      // prologue
    pdl_wait();                                  // g_p2 ready
    pdl_trigger();
    if (i < NE) {
        float2 v = *reinterpret_cast<const float2*>(&g_p2[r]);
        atomicAdd(&g_acc[c], v);
    }
}

// ---- node passes ----

__global__ void __launch_bounds__(256) k_node1(const float* __restrict__ x) {
    int i = blockIdx.x * blockDim.x + threadIdx.x;
    float xv = (i < NN) ? x[i] : 0.f;            // prologue: x independent of count
    pdl_wait();                                  // g_deg ready
    pdl_trigger();
    if (i >= NN) return;
    float dinv = rsqrtf((float)(g_deg[i] + 1));
    g_dinv[i] = dinv;
    g_p[i]    = xv * dinv;
}

__global__ void __launch_bounds__(256) k_node2(const float* __restrict__ W1,
                                               const float* __restrict__ b1,
                                               const float* __restrict__ W2) {
    __shared__ float sW1[HID], sb1[HID], sW2[HID * 2];
    int t = threadIdx.x;
    // prologue: stage weights (independent of scat1) — overlaps with scat1
    if (t < HID)     { sW1[t] = W1[t]; sb1[t] = b1[t]; }
    if (t < HID * 2) { sW2[t] = W2[t]; }
    __syncthreads();
    pdl_wait();                                  // g_s1 ready
    pdl_trigger();

    int i = blockIdx.x * blockDim.x + t;
    if (i >= NN) return;
    float dinv = g_dinv[i];
    float s1   = dinv * (g_s1[i] + g_p[i]);
    float a = 0.f, b = 0.f;
#pragma unroll
    for (int j = 0; j < HID; ++j) {
        float h = fmaxf(fmaf(sW1[j], s1, sb1[j]), 0.f);
        a = fmaf(h, sW2[2 * j],     a);
        b = fmaf(h, sW2[2 * j + 1], b);
    }
    g_p2[i] = make_float2(a * dinv, b * dinv);
}

__global__ void __launch_bounds__(256) k_final(float* __restrict__ out,
                                               const float* __restrict__ b2) {
    int i = blockIdx.x * blockDim.x + threadIdx.x;
    float b2x = b2[0], b2y = b2[1];              // prologue
    pdl_wait();                                  // g_acc ready
    pdl_trigger();
    if (i >= NN) return;
    float dinv = g_dinv[i];
    float2 acc = g_acc[i];
    float2 p2  = g_p2[i];
    float2 o;
    o.x = fmaf(dinv, acc.x + p2.x, b2x);
    o.y = fmaf(dinv, acc.y + p2.y, b2y);
    reinterpret_cast<float2*>(out)[i] = o;

    // restore the all-zeros invariant for the next replay
    g_deg[i] = 0;
    g_s1[i]  = 0.f;
    g_acc[i] = make_float2(0.f, 0.f);
}

// ---- host: PDL launches (graph-capturable) ----

static void launch_pdl(const void* fn, int grid, int block, void** args) {
    cudaLaunchConfig_t cfg = {};
    cfg.gridDim  = dim3(grid, 1, 1);
    cfg.blockDim = dim3(block, 1, 1);
    cfg.stream   = 0;
    cudaLaunchAttribute attr[1];
    attr[0].id = cudaLaunchAttributeProgrammaticStreamSerialization;
    attr[0].val.programmaticStreamSerializationAllowed = 1;
    cfg.attrs    = attr;
    cfg.numAttrs = 1;
    cudaLaunchKernelExC(&cfg, fn, args);
}

extern "C" void kernel_launch(void* const* d_in, const int* in_sizes, int n_in,
                              void* d_out, int out_size) {
    const float* x   = (const float*)d_in[0];
    const int*   ei  = (const int*)d_in[1];   // [2, NE]
    const float* W1  = (const float*)d_in[2];
    const float* b1  = (const float*)d_in[3];
    const float* W2  = (const float*)d_in[4];
    const float* b2  = (const float*)d_in[5];
    float* out = (float*)d_out;

    const int* row = ei;
    const int* col = ei + NE;

    const int TB = 256;
    const int nodeBlocks = (NN + TB - 1) / TB;
    const int edgeBlocks = (NE + TB - 1) / TB;

    { void* a[] = { (void*)&col };                              launch_pdl((const void*)k_count, edgeBlocks, TB, a); }
    { void* a[] = { (void*)&x };                                launch_pdl((const void*)k_node1, nodeBlocks, TB, a); }
    { void* a[] = { (void*)&row, (void*)&col };                 launch_pdl((const void*)k_scat1, edgeBlocks, TB, a); }
    { void* a[] = { (void*)&W1, (void*)&b1, (void*)&W2 };       launch_pdl((const void*)k_node2, nodeBlocks, TB, a); }
    { void* a[] = { (void*)&row, (void*)&col };                 launch_pdl((const void*)k_scat2, edgeBlocks, TB, a); }
    { void* a[] = { (void*)&out, (void*)&b2 };                  launch_pdl((const void*)k_final, nodeBlocks, TB, a); }
}